// round 1
// baseline (speedup 1.0000x reference)
#include <cuda_runtime.h>
#include <math.h>

#define Bdim 8
#define Sdim 4096
#define Ddim 512
#define Mrows (Bdim * Sdim)   /* 32768 */
#define NC 32
#define CL (Sdim / NC)        /* 128 */

// ---------------------------------------------------------------------------
// Scratch (device globals — no allocation allowed)
// ---------------------------------------------------------------------------
__device__ float g_omega[(size_t)Mrows * Ddim];
__device__ float g_mag  [(size_t)Mrows * Ddim];
__device__ float g_gate [(size_t)Mrows * Ddim];
__device__ float g_qoff [(size_t)Mrows * Ddim];
__device__ float g_p1h  [(size_t)Mrows * Ddim];
__device__ float g_phii [(size_t)Mrows * Ddim];
__device__ float g_ctx  [(size_t)Mrows * 4 * Ddim];
__device__ float g_h    [(size_t)Mrows * 2 * Ddim];
__device__ float4 g_csum[Bdim * NC * Ddim];
__device__ float4 g_coff[Bdim * NC * Ddim];

// ---------------------------------------------------------------------------
// Packed f32x2 helpers (sm_103a: scalar FFMA is half-rate; f32x2 is full-rate)
// ---------------------------------------------------------------------------
__device__ __forceinline__ unsigned long long bcast2(float v) {
    unsigned long long r;
    unsigned u = __float_as_uint(v);
    asm("mov.b64 %0, {%1, %1};" : "=l"(r) : "r"(u));
    return r;
}
__device__ __forceinline__ void fma2(unsigned long long& d,
                                     unsigned long long a,
                                     unsigned long long b) {
    asm("fma.rn.f32x2 %0, %1, %2, %0;" : "+l"(d) : "l"(a), "l"(b));
}
__device__ __forceinline__ void unpack2(unsigned long long v, float& lo, float& hi) {
    unsigned a, b;
    asm("mov.b64 {%0, %1}, %2;" : "=r"(a), "=r"(b) : "l"(v));
    lo = __uint_as_float(a);
    hi = __uint_as_float(b);
}

// ---------------------------------------------------------------------------
// SGEMM: C[M,N] = act(A[M,K] @ W[K,N] + bias[N]) (+ resid for ACT==4)
// BM=BN=128, BK=8, 256 threads, 8x8 per thread, double-buffered smem,
// f32x2 packed inner product.
// ACT: 0=none 1=sigmoid 2=5*sigmoid 3=gelu(exact) 4=residual add
// Requires: M%128==0, N%128==0, K%8==0 (true for all launches here).
// ---------------------------------------------------------------------------
template <int ACT>
__global__ void __launch_bounds__(256, 2)
sgemm_kernel(const float* __restrict__ A,
             const float* __restrict__ W,
             const float* __restrict__ bias,
             const float* __restrict__ resid,
             float* __restrict__ C,
             int M, int N, int K)
{
    __shared__ float As[2][8][128];
    __shared__ float Bs[2][8][128];

    const int tid = threadIdx.x;
    const int tx = tid & 15;
    const int ty = tid >> 4;
    const int bn = blockIdx.x * 128;
    const int bm = blockIdx.y * 128;

    const int arow = tid >> 1;
    const int acol = (tid & 1) << 2;
    const int brow = tid >> 5;
    const int bcol = (tid & 31) << 2;

    const float* Aptr = A + (size_t)(bm + arow) * K + acol;
    const float* Wptr = W + (size_t)brow * N + bn + bcol;

    float4 av = *(const float4*)Aptr;
    float4 bv = *(const float4*)Wptr;
    As[0][acol + 0][arow] = av.x;
    As[0][acol + 1][arow] = av.y;
    As[0][acol + 2][arow] = av.z;
    As[0][acol + 3][arow] = av.w;
    *(float4*)&Bs[0][brow][bcol] = bv;
    __syncthreads();

    unsigned long long acc2[8][4];
    #pragma unroll
    for (int i = 0; i < 8; i++)
        #pragma unroll
        for (int p = 0; p < 4; p++) acc2[i][p] = 0ull;

    const int nk = K >> 3;
    for (int kt = 0; kt < nk; kt++) {
        const int cur = kt & 1;
        if (kt + 1 < nk) {
            av = *(const float4*)(Aptr + (kt + 1) * 8);
            bv = *(const float4*)(Wptr + (size_t)(kt + 1) * 8 * N);
        }
        #pragma unroll
        for (int k = 0; k < 8; k++) {
            float4 a0 = *(const float4*)&As[cur][k][ty * 8];
            float4 a1 = *(const float4*)&As[cur][k][ty * 8 + 4];
            ulonglong2 bq0 = *(const ulonglong2*)&Bs[cur][k][tx * 8];
            ulonglong2 bq1 = *(const ulonglong2*)&Bs[cur][k][tx * 8 + 4];
            unsigned long long aa[8];
            aa[0] = bcast2(a0.x); aa[1] = bcast2(a0.y);
            aa[2] = bcast2(a0.z); aa[3] = bcast2(a0.w);
            aa[4] = bcast2(a1.x); aa[5] = bcast2(a1.y);
            aa[6] = bcast2(a1.z); aa[7] = bcast2(a1.w);
            #pragma unroll
            for (int i = 0; i < 8; i++) {
                fma2(acc2[i][0], aa[i], bq0.x);
                fma2(acc2[i][1], aa[i], bq0.y);
                fma2(acc2[i][2], aa[i], bq1.x);
                fma2(acc2[i][3], aa[i], bq1.y);
            }
        }
        if (kt + 1 < nk) {
            const int nxt = cur ^ 1;
            As[nxt][acol + 0][arow] = av.x;
            As[nxt][acol + 1][arow] = av.y;
            As[nxt][acol + 2][arow] = av.z;
            As[nxt][acol + 3][arow] = av.w;
            *(float4*)&Bs[nxt][brow][bcol] = bv;
        }
        __syncthreads();
    }

    // Epilogue
    const float4 bias0 = *(const float4*)(bias + bn + tx * 8);
    const float4 bias1 = *(const float4*)(bias + bn + tx * 8 + 4);
    const float bb[8] = {bias0.x, bias0.y, bias0.z, bias0.w,
                         bias1.x, bias1.y, bias1.z, bias1.w};
    #pragma unroll
    for (int i = 0; i < 8; i++) {
        const int m = bm + ty * 8 + i;
        const size_t rowoff = (size_t)m * N + bn + tx * 8;
        float vals[8];
        #pragma unroll
        for (int p = 0; p < 4; p++)
            unpack2(acc2[i][p], vals[2 * p], vals[2 * p + 1]);
        #pragma unroll
        for (int j = 0; j < 8; j++) {
            float v = vals[j] + bb[j];
            if (ACT == 1) v = 1.0f / (1.0f + expf(-v));
            else if (ACT == 2) v = 5.0f / (1.0f + expf(-v));
            else if (ACT == 3) v = 0.5f * v * (1.0f + erff(v * 0.70710678118654752f));
            vals[j] = v;
        }
        if (ACT == 4) {
            float4 r0 = *(const float4*)(resid + rowoff);
            float4 r1 = *(const float4*)(resid + rowoff + 4);
            vals[0] += r0.x; vals[1] += r0.y; vals[2] += r0.z; vals[3] += r0.w;
            vals[4] += r1.x; vals[5] += r1.y; vals[6] += r1.z; vals[7] += r1.w;
        }
        float4 o0 = make_float4(vals[0], vals[1], vals[2], vals[3]);
        float4 o1 = make_float4(vals[4], vals[5], vals[6], vals[7]);
        *(float4*)&C[rowoff] = o0;
        *(float4*)&C[rowoff + 4] = o1;
    }
}

// ---------------------------------------------------------------------------
// Pass A: per-(b, chunk, d) local scan -> chunk sums
// (S_inc, S_mag, A = sum wc*cos(phi_local), B = sum wc*sin(phi_local))
// ---------------------------------------------------------------------------
__global__ void __launch_bounds__(Ddim)
passA_kernel(const float* __restrict__ x,
             const float* __restrict__ omega,
             const float* __restrict__ mag,
             const float* __restrict__ gate,
             const float* __restrict__ phii,
             const float* __restrict__ iscale,
             float4* __restrict__ csum)
{
    const int b = blockIdx.x / NC;
    const int c = blockIdx.x % NC;
    const int d = threadIdx.x;
    const float sc = fabsf(iscale[d]);
    size_t idx = ((size_t)b * Sdim + (size_t)c * CL) * Ddim + d;
    float rinc = 0.f, rmag = 0.f, rA = 0.f, rB = 0.f;
    #pragma unroll 4
    for (int s = 0; s < CL; s++, idx += Ddim) {
        float g = gate[idx], om = omega[idx], m = mag[idx];
        float xv = x[idx], pi = phii[idx];
        rinc += g * om * sc;
        float sp, cp;
        sincosf(pi + rinc, &sp, &cp);
        float wc = m * xv;
        rA += wc * cp;
        rB += wc * sp;
        rmag += m;
    }
    csum[(size_t)blockIdx.x * Ddim + d] = make_float4(rinc, rmag, rA, rB);
}

// ---------------------------------------------------------------------------
// Pass B: cross-chunk exclusive scan per (b,d) with trig rotation composition
// ---------------------------------------------------------------------------
__global__ void __launch_bounds__(Ddim)
passB_kernel(const float4* __restrict__ csum, float4* __restrict__ coff)
{
    const int b = blockIdx.x;
    const int d = threadIdx.x;
    float oi = 0.f, om = 0.f, omr = 0.f, omi = 0.f;
    #pragma unroll 4
    for (int c = 0; c < NC; c++) {
        const size_t i = ((size_t)b * NC + c) * Ddim + d;
        coff[i] = make_float4(oi, om, omr, omi);
        float4 s = csum[i];
        float st, ct;
        sincosf(oi, &st, &ct);
        omr += ct * s.z - st * s.w;
        omi += st * s.z + ct * s.w;
        oi += s.x;
        om += s.y;
    }
}

// ---------------------------------------------------------------------------
// Pass C: final scan + retrieval + fused LayerNorm over 4D=2048 (block-wide),
// writes normalized context [32768, 2048] ready for the W_o1 GEMM.
// Block = one (b, chunk); 512 threads = all d. For each s, the block holds
// all 2048 context values -> block reduction gives mean/var.
// ---------------------------------------------------------------------------
__global__ void __launch_bounds__(Ddim)
passC_kernel(const float* __restrict__ x,
             const float* __restrict__ omega,
             const float* __restrict__ mag,
             const float* __restrict__ gate,
             const float* __restrict__ phii,
             const float* __restrict__ qoffp,
             const float* __restrict__ iscale,
             const float* __restrict__ lng,
             const float* __restrict__ lnb,
             const float4* __restrict__ coff,
             float* __restrict__ ctx)
{
    __shared__ float2 warpred[16];
    __shared__ float2 bcast;
    const int b = blockIdx.x / NC;
    const int c = blockIdx.x % NC;
    const int d = threadIdx.x;
    const int lane = d & 31;
    const int wid = d >> 5;
    const float sc = fabsf(iscale[d]);
    const float g0 = lng[d],        g1 = lng[Ddim + d];
    const float g2 = lng[2*Ddim+d], g3 = lng[3*Ddim + d];
    const float l0 = lnb[d],        l1 = lnb[Ddim + d];
    const float l2 = lnb[2*Ddim+d], l3 = lnb[3*Ddim + d];

    float4 off = coff[(size_t)blockIdx.x * Ddim + d];
    float rinc = off.x, rmag = off.y, rmr = off.z, rmi = off.w;

    size_t idx   = ((size_t)b * Sdim + (size_t)c * CL) * Ddim + d;
    size_t cbase = ((size_t)b * Sdim + (size_t)c * CL) * (4 * Ddim) + d;

    for (int s = 0; s < CL; s++, idx += Ddim, cbase += 4 * Ddim) {
        float g = gate[idx], om = omega[idx], m = mag[idx];
        float xv = x[idx], pi = phii[idx], qo = qoffp[idx];
        rinc += g * om * sc;
        float phi = pi + rinc;
        float sp, cp;
        sincosf(phi, &sp, &cp);
        float wc = m * xv;
        rmr += wc * cp;
        rmi += wc * sp;
        rmag += m;
        float rq = rsqrtf(rmag + 1e-8f);
        float mrv = rmr * rq, miv = rmi * rq;
        float sq, cq;
        sincosf(phi + qo, &sq, &cq);
        float v0 = xv * cp, v1 = xv * sp;
        float v2 = mrv * cq + miv * sq;
        float v3 = miv * cq - mrv * sq;

        // LayerNorm reduction across the block (2048 values for this s)
        float lsum = v0 + v1 + v2 + v3;
        float lss  = v0 * v0 + v1 * v1 + v2 * v2 + v3 * v3;
        #pragma unroll
        for (int o = 16; o > 0; o >>= 1) {
            lsum += __shfl_down_sync(0xffffffffu, lsum, o);
            lss  += __shfl_down_sync(0xffffffffu, lss, o);
        }
        if (lane == 0) warpred[wid] = make_float2(lsum, lss);
        __syncthreads();
        if (wid == 0) {
            float2 t = (lane < 16) ? warpred[lane] : make_float2(0.f, 0.f);
            #pragma unroll
            for (int o = 8; o > 0; o >>= 1) {
                t.x += __shfl_down_sync(0xffffffffu, t.x, o);
                t.y += __shfl_down_sync(0xffffffffu, t.y, o);
            }
            if (lane == 0) bcast = t;
        }
        __syncthreads();
        const float mean = bcast.x * (1.0f / 2048.0f);
        const float var  = bcast.y * (1.0f / 2048.0f) - mean * mean;
        const float rstd = rsqrtf(var + 1e-5f);

        ctx[cbase           ] = (v0 - mean) * rstd * g0 + l0;
        ctx[cbase + Ddim    ] = (v1 - mean) * rstd * g1 + l1;
        ctx[cbase + 2 * Ddim] = (v2 - mean) * rstd * g2 + l2;
        ctx[cbase + 3 * Ddim] = (v3 - mean) * rstd * g3 + l3;
    }
}

// ---------------------------------------------------------------------------
// Launch
// ---------------------------------------------------------------------------
extern "C" void kernel_launch(void* const* d_in, const int* in_sizes, int n_in,
                              void* d_out, int out_size)
{
    const float* x       = (const float*)d_in[0];
    const float* W_omega = (const float*)d_in[1];
    const float* b_omega = (const float*)d_in[2];
    const float* W_p1    = (const float*)d_in[3];
    const float* b_p1    = (const float*)d_in[4];
    const float* W_p2    = (const float*)d_in[5];
    const float* b_p2    = (const float*)d_in[6];
    const float* W_gate  = (const float*)d_in[7];
    const float* b_gate  = (const float*)d_in[8];
    const float* iscale  = (const float*)d_in[9];
    const float* W_mag   = (const float*)d_in[10];
    const float* b_mag   = (const float*)d_in[11];
    const float* W_qoff  = (const float*)d_in[12];
    const float* b_qoff  = (const float*)d_in[13];
    const float* ln_g    = (const float*)d_in[14];
    const float* ln_b    = (const float*)d_in[15];
    const float* W_o1    = (const float*)d_in[16];
    const float* b_o1    = (const float*)d_in[17];
    const float* W_o2    = (const float*)d_in[18];
    const float* b_o2    = (const float*)d_in[19];
    float* out = (float*)d_out;

    float *p_omega, *p_mag, *p_gate, *p_qoff, *p_p1h, *p_phii, *p_ctx, *p_h;
    float4 *p_csum, *p_coff;
    cudaGetSymbolAddress((void**)&p_omega, g_omega);
    cudaGetSymbolAddress((void**)&p_mag,   g_mag);
    cudaGetSymbolAddress((void**)&p_gate,  g_gate);
    cudaGetSymbolAddress((void**)&p_qoff,  g_qoff);
    cudaGetSymbolAddress((void**)&p_p1h,   g_p1h);
    cudaGetSymbolAddress((void**)&p_phii,  g_phii);
    cudaGetSymbolAddress((void**)&p_ctx,   g_ctx);
    cudaGetSymbolAddress((void**)&p_h,     g_h);
    cudaGetSymbolAddress((void**)&p_csum,  g_csum);
    cudaGetSymbolAddress((void**)&p_coff,  g_coff);

    const dim3 blk(256);
    const dim3 gP(512 / 128, Mrows / 128);   // projections: N=512
    const dim3 gO1(1024 / 128, Mrows / 128); // W_o1: N=1024
    const dim3 gO2(512 / 128, Mrows / 128);  // W_o2: N=512

    // Projections
    sgemm_kernel<0><<<gP, blk>>>(x, W_omega, b_omega, nullptr, p_omega, Mrows, 512, 512);
    sgemm_kernel<2><<<gP, blk>>>(x, W_mag,   b_mag,   nullptr, p_mag,   Mrows, 512, 512);
    sgemm_kernel<1><<<gP, blk>>>(x, W_gate,  b_gate,  nullptr, p_gate,  Mrows, 512, 512);
    sgemm_kernel<0><<<gP, blk>>>(x, W_qoff,  b_qoff,  nullptr, p_qoff,  Mrows, 512, 512);
    sgemm_kernel<3><<<gP, blk>>>(x, W_p1,    b_p1,    nullptr, p_p1h,   Mrows, 512, 512);
    sgemm_kernel<0><<<gP, blk>>>(p_p1h, W_p2, b_p2,   nullptr, p_phii,  Mrows, 512, 512);

    // Decoupled sequence scan + fused LN context build
    passA_kernel<<<Bdim * NC, Ddim>>>(x, p_omega, p_mag, p_gate, p_phii, iscale, p_csum);
    passB_kernel<<<Bdim, Ddim>>>(p_csum, p_coff);
    passC_kernel<<<Bdim * NC, Ddim>>>(x, p_omega, p_mag, p_gate, p_phii, p_qoff,
                                      iscale, ln_g, ln_b, p_coff, p_ctx);

    // Output MLP
    sgemm_kernel<3><<<gO1, blk>>>(p_ctx, W_o1, b_o1, nullptr, p_h, Mrows, 1024, 2048);
    sgemm_kernel<4><<<gO2, blk>>>(p_h, W_o2, b_o2, x, out, Mrows, 512, 1024);
}